// round 5
// baseline (speedup 1.0000x reference)
#include <cuda_runtime.h>
#include <cstdint>

// Problem constants (fixed by the dataset)
#define BB   16
#define NN   4096
#define SS   1024
#define KK   32
#define DIN  64
#define DINC 67
#define DOUT 64

#define ROWS 256          // rows per proj block
#define RP   258          // padded row-stride for transposed x tile

#define NCHUNK 4          // batch chunks for proj/pool overlap
#define PROJ_BLKS_PER_CHUNK ((BB * NN) / ROWS / NCHUNK)   // 64
#define POOL_BLKS_PER_CHUNK ((BB * SS) / 16 / NCHUNK)     // 256

// Scratch (static device globals: allocation-free per harness rules)
__device__ float g_sum[(size_t)BB * NN * DOUT];   // xc@W1 + bias (+ xp if use_x)
__device__ float g_xp [(size_t)BB * NN * DOUT];   // xp = x@W2 (center subtraction)

typedef unsigned long long ull;

// ---------------------------------------------------------------------------
// Packed f32x2 helpers
// ---------------------------------------------------------------------------
__device__ __forceinline__ void ffma2(ull& d, ull a, ull b) {
    asm("fma.rn.f32x2 %0, %1, %2, %0;" : "+l"(d) : "l"(a), "l"(b));
}
__device__ __forceinline__ ull dup2(float x) {
    ull r;
    unsigned int xi = __float_as_uint(x);
    asm("mov.b64 %0, {%1, %1};" : "=l"(r) : "r"(xi));
    return r;
}
__device__ __forceinline__ float2 asf2(ull v) {
    float2 f;
    asm("mov.b64 {%0, %1}, %2;" : "=f"(f.x), "=f"(f.y) : "l"(v));
    return f;
}

// ---------------------------------------------------------------------------
// Proj kernel (round-3 structure; FFMA2-pipe bound):
//   phase A (if use_x): acc  = x[rows] @ W2^T          -> write g_xp
//   phase B:            acc += xc[rows] @ W1^T (+bias) -> write g_sum
// blk_base shifts the block id so the grid can be launched per batch-chunk.
// ---------------------------------------------------------------------------
__global__ void __launch_bounds__(256, 2) proj_kernel(
    const float* __restrict__ x, const float* __restrict__ xcm,
    const float* __restrict__ w1, const float* __restrict__ w2,
    const float* __restrict__ bias, const int* __restrict__ use_x,
    int blk_base)
{
    extern __shared__ float sm[];
    float* sW1 = sm;                       // [67][64]  k-major
    float* sW2 = sW1 + DINC * DOUT;        // [64][64]  k-major
    float* sB  = sW2 + DIN  * DOUT;        // [64]
    float* sXT = sB  + 64;                 // [67][RP]  transposed input tile

    const int tid = threadIdx.x;

    for (int i = tid; i < DOUT * DINC; i += 256) {
        int c = i / DINC, k = i % DINC;
        sW1[k * DOUT + c] = w1[i];
    }
    for (int i = tid; i < DOUT * DIN; i += 256) {
        int c = i >> 6, k = i & 63;
        sW2[k * DOUT + c] = w2[i];
    }
    if (tid < DOUT) sB[tid] = bias[tid];
    const int ux = use_x[0];

    const size_t base = (size_t)(blockIdx.x + blk_base) * ROWS;
    const int cg = tid & 7;
    const int rg = tid >> 3;
    const int c0 = cg * 8;
    const int r0 = rg * 8;

    ull acc[4][8];
    #pragma unroll
    for (int i = 0; i < 4; i++)
        #pragma unroll
        for (int c = 0; c < 8; c++) acc[i][c] = 0ULL;

    // ---------------- Phase A: xp = x @ W2^T ----------------
    if (ux) {
        const float* xg = x + base * DIN;
        for (int i = tid; i < ROWS * DIN; i += 256) {
            int r = i >> 6, k = i & 63;
            sXT[k * RP + r] = xg[i];
        }
        __syncthreads();

        #pragma unroll 4
        for (int k = 0; k < DIN; k++) {
            const float* xr = sXT + k * RP + r0;
            ull x01 = *(const ull*)(xr);
            ull x23 = *(const ull*)(xr + 2);
            ull x45 = *(const ull*)(xr + 4);
            ull x67 = *(const ull*)(xr + 6);
            float4 wa = *(const float4*)(sW2 + k * DOUT + c0);
            float4 wb = *(const float4*)(sW2 + k * DOUT + c0 + 4);
            ull wd0 = dup2(wa.x), wd1 = dup2(wa.y), wd2 = dup2(wa.z), wd3 = dup2(wa.w);
            ull wd4 = dup2(wb.x), wd5 = dup2(wb.y), wd6 = dup2(wb.z), wd7 = dup2(wb.w);
            ffma2(acc[0][0], x01, wd0); ffma2(acc[0][1], x01, wd1); ffma2(acc[0][2], x01, wd2); ffma2(acc[0][3], x01, wd3);
            ffma2(acc[0][4], x01, wd4); ffma2(acc[0][5], x01, wd5); ffma2(acc[0][6], x01, wd6); ffma2(acc[0][7], x01, wd7);
            ffma2(acc[1][0], x23, wd0); ffma2(acc[1][1], x23, wd1); ffma2(acc[1][2], x23, wd2); ffma2(acc[1][3], x23, wd3);
            ffma2(acc[1][4], x23, wd4); ffma2(acc[1][5], x23, wd5); ffma2(acc[1][6], x23, wd6); ffma2(acc[1][7], x23, wd7);
            ffma2(acc[2][0], x45, wd0); ffma2(acc[2][1], x45, wd1); ffma2(acc[2][2], x45, wd2); ffma2(acc[2][3], x45, wd3);
            ffma2(acc[2][4], x45, wd4); ffma2(acc[2][5], x45, wd5); ffma2(acc[2][6], x45, wd6); ffma2(acc[2][7], x45, wd7);
            ffma2(acc[3][0], x67, wd0); ffma2(acc[3][1], x67, wd1); ffma2(acc[3][2], x67, wd2); ffma2(acc[3][3], x67, wd3);
            ffma2(acc[3][4], x67, wd4); ffma2(acc[3][5], x67, wd5); ffma2(acc[3][6], x67, wd6); ffma2(acc[3][7], x67, wd7);
        }

        #pragma unroll
        for (int rp = 0; rp < 4; rp++) {
            float2 f[8];
            #pragma unroll
            for (int c = 0; c < 8; c++) f[c] = asf2(acc[rp][c]);
            size_t rowA = base + r0 + 2 * rp;
            float* p0 = g_xp + rowA * DOUT + c0;
            float* p1 = p0 + DOUT;
            *(float4*)(p0)     = make_float4(f[0].x, f[1].x, f[2].x, f[3].x);
            *(float4*)(p0 + 4) = make_float4(f[4].x, f[5].x, f[6].x, f[7].x);
            *(float4*)(p1)     = make_float4(f[0].y, f[1].y, f[2].y, f[3].y);
            *(float4*)(p1 + 4) = make_float4(f[4].y, f[5].y, f[6].y, f[7].y);
        }
        __syncthreads();
    }

    // ---------------- Phase B: acc += xc @ W1^T ----------------
    {
        const float* xcg = xcm + base * DINC;
        for (int i = tid; i < ROWS * DINC; i += 256) {
            int r = i / DINC, k = i % DINC;
            sXT[k * RP + r] = xcg[i];
        }
        __syncthreads();

        #pragma unroll 4
        for (int k = 0; k < DINC; k++) {
            const float* xr = sXT + k * RP + r0;
            ull x01 = *(const ull*)(xr);
            ull x23 = *(const ull*)(xr + 2);
            ull x45 = *(const ull*)(xr + 4);
            ull x67 = *(const ull*)(xr + 6);
            float4 wa = *(const float4*)(sW1 + k * DOUT + c0);
            float4 wb = *(const float4*)(sW1 + k * DOUT + c0 + 4);
            ull wd0 = dup2(wa.x), wd1 = dup2(wa.y), wd2 = dup2(wa.z), wd3 = dup2(wa.w);
            ull wd4 = dup2(wb.x), wd5 = dup2(wb.y), wd6 = dup2(wb.z), wd7 = dup2(wb.w);
            ffma2(acc[0][0], x01, wd0); ffma2(acc[0][1], x01, wd1); ffma2(acc[0][2], x01, wd2); ffma2(acc[0][3], x01, wd3);
            ffma2(acc[0][4], x01, wd4); ffma2(acc[0][5], x01, wd5); ffma2(acc[0][6], x01, wd6); ffma2(acc[0][7], x01, wd7);
            ffma2(acc[1][0], x23, wd0); ffma2(acc[1][1], x23, wd1); ffma2(acc[1][2], x23, wd2); ffma2(acc[1][3], x23, wd3);
            ffma2(acc[1][4], x23, wd4); ffma2(acc[1][5], x23, wd5); ffma2(acc[1][6], x23, wd6); ffma2(acc[1][7], x23, wd7);
            ffma2(acc[2][0], x45, wd0); ffma2(acc[2][1], x45, wd1); ffma2(acc[2][2], x45, wd2); ffma2(acc[2][3], x45, wd3);
            ffma2(acc[2][4], x45, wd4); ffma2(acc[2][5], x45, wd5); ffma2(acc[2][6], x45, wd6); ffma2(acc[2][7], x45, wd7);
            ffma2(acc[3][0], x67, wd0); ffma2(acc[3][1], x67, wd1); ffma2(acc[3][2], x67, wd2); ffma2(acc[3][3], x67, wd3);
            ffma2(acc[3][4], x67, wd4); ffma2(acc[3][5], x67, wd5); ffma2(acc[3][6], x67, wd6); ffma2(acc[3][7], x67, wd7);
        }
    }

    {
        float4 ba = *(const float4*)(sB + c0);
        float4 bb = *(const float4*)(sB + c0 + 4);
        #pragma unroll
        for (int rp = 0; rp < 4; rp++) {
            float2 f[8];
            #pragma unroll
            for (int c = 0; c < 8; c++) f[c] = asf2(acc[rp][c]);
            size_t rowA = base + r0 + 2 * rp;
            float* p0 = g_sum + rowA * DOUT + c0;
            float* p1 = p0 + DOUT;
            *(float4*)(p0)     = make_float4(f[0].x + ba.x, f[1].x + ba.y, f[2].x + ba.z, f[3].x + ba.w);
            *(float4*)(p0 + 4) = make_float4(f[4].x + bb.x, f[5].x + bb.y, f[6].x + bb.z, f[7].x + bb.w);
            *(float4*)(p1)     = make_float4(f[0].y + ba.x, f[1].y + ba.y, f[2].y + ba.z, f[3].y + ba.w);
            *(float4*)(p1 + 4) = make_float4(f[4].y + bb.x, f[5].y + bb.y, f[6].y + bb.z, f[7].y + bb.w);
        }
    }
}

// ---------------------------------------------------------------------------
// Pool kernel (round-3 structure, near L2-traffic floor) with blk_base offset
// so each chunk runs as soon as its batches' projections are done.
// ---------------------------------------------------------------------------
__global__ void __launch_bounds__(256) pool_kernel(
    const void* __restrict__ indexes, const int* __restrict__ use_x,
    float* __restrict__ out, int blk_base)
{
    __shared__ int sidx[512];           // 16 pairs x 32 idx
    const int tid = threadIdx.x;
    const size_t blk = (size_t)(blockIdx.x + blk_base);

    // Detection read: in-bounds under BOTH dtype interpretations.
    int2 v = ((const int2*)indexes)[blk * 256 + tid];
    bool pok = (v.y == (v.x < 0 ? -1 : 0));
    int is64 = __syncthreads_and(pok);

    if (is64) {
        longlong2 q = ((const longlong2*)indexes)[blk * 256 + tid];
        sidx[2 * tid]     = (int)q.x;
        sidx[2 * tid + 1] = (int)q.y;
    } else {
        sidx[2 * tid]     = v.x;
        sidx[2 * tid + 1] = v.y;
    }
    __syncthreads();

    const int grp    = tid >> 4;
    const int lane16 = tid & 15;
    const size_t p   = blk * 16 + grp;
    const int b      = (int)(p >> 10);
    const int* myidx = sidx + grp * 32;

    const float* sumb = g_sum + (size_t)b * NN * DOUT;
    const int c0 = lane16 * 4;
    const int id0 = myidx[0];

    const int ux = use_x[0];
    float4 cen = make_float4(0.f, 0.f, 0.f, 0.f);
    if (ux)
        cen = *(const float4*)(g_xp + ((size_t)b * NN + id0) * DOUT + c0);

    float4 a[8];
    #pragma unroll
    for (int q = 0; q < 8; q++) a[q] = make_float4(-3.4e38f, -3.4e38f, -3.4e38f, -3.4e38f);

    #pragma unroll
    for (int q = 0; q < 8; q++) {
        int4 iq = ((const int4*)myidx)[q];
        int j0 = iq.x < 0 ? id0 : iq.x;
        int j1 = iq.y < 0 ? id0 : iq.y;
        int j2 = iq.z < 0 ? id0 : iq.z;
        int j3 = iq.w < 0 ? id0 : iq.w;
        float4 v0 = *(const float4*)(sumb + (size_t)j0 * DOUT + c0);
        float4 v1 = *(const float4*)(sumb + (size_t)j1 * DOUT + c0);
        float4 v2 = *(const float4*)(sumb + (size_t)j2 * DOUT + c0);
        float4 v3 = *(const float4*)(sumb + (size_t)j3 * DOUT + c0);
        float4 m01, m23;
        m01.x = fmaxf(v0.x, v1.x); m01.y = fmaxf(v0.y, v1.y); m01.z = fmaxf(v0.z, v1.z); m01.w = fmaxf(v0.w, v1.w);
        m23.x = fmaxf(v2.x, v3.x); m23.y = fmaxf(v2.y, v3.y); m23.z = fmaxf(v2.z, v3.z); m23.w = fmaxf(v2.w, v3.w);
        a[q].x = fmaxf(m01.x, m23.x); a[q].y = fmaxf(m01.y, m23.y);
        a[q].z = fmaxf(m01.z, m23.z); a[q].w = fmaxf(m01.w, m23.w);
    }

    #pragma unroll
    for (int st = 4; st > 0; st >>= 1)
        #pragma unroll
        for (int q = 0; q < st; q++) {
            a[q].x = fmaxf(a[q].x, a[q + st].x);
            a[q].y = fmaxf(a[q].y, a[q + st].y);
            a[q].z = fmaxf(a[q].z, a[q + st].z);
            a[q].w = fmaxf(a[q].w, a[q + st].w);
        }

    float4 o = make_float4(a[0].x - cen.x, a[0].y - cen.y, a[0].z - cen.z, a[0].w - cen.w);
    *(float4*)(out + p * DOUT + c0) = o;
}

// ---------------------------------------------------------------------------
// Launcher: 4 batch-chunks; proj chunks on the capturing (legacy) stream,
// pool chunks on a second non-blocking stream gated by per-chunk events.
// Stream/event creation happens once, on the first (uncaptured) correctness
// call; captured calls contain only launches + event record/wait edges.
// ---------------------------------------------------------------------------
extern "C" void kernel_launch(void* const* d_in, const int* in_sizes, int n_in,
                              void* d_out, int out_size)
{
    const float* x    = (const float*)d_in[0];
    const float* xcm  = (const float*)d_in[1];
    const void*  idx  = d_in[2];
    const float* w1   = (const float*)d_in[3];
    const float* w2   = (const float*)d_in[4];
    const float* bias = (const float*)d_in[5];
    const int*   ux   = (const int*)d_in[6];

    static cudaStream_t s2 = nullptr;
    static cudaEvent_t  ev[NCHUNK];
    static cudaEvent_t  evJoin = nullptr;
    if (s2 == nullptr) {
        cudaStreamCreateWithFlags(&s2, cudaStreamNonBlocking);
        for (int c = 0; c < NCHUNK; c++)
            cudaEventCreateWithFlags(&ev[c], cudaEventDisableTiming);
        cudaEventCreateWithFlags(&evJoin, cudaEventDisableTiming);
    }

    const int smem_bytes = (DINC * DOUT + DIN * DOUT + 64 + DINC * RP) * 4;   // 102,936 B
    cudaFuncSetAttribute(proj_kernel, cudaFuncAttributeMaxDynamicSharedMemorySize, smem_bytes);

    for (int c = 0; c < NCHUNK; c++) {
        proj_kernel<<<PROJ_BLKS_PER_CHUNK, 256, smem_bytes>>>(
            x, xcm, w1, w2, bias, ux, c * PROJ_BLKS_PER_CHUNK);
        cudaEventRecord(ev[c], 0);
        cudaStreamWaitEvent(s2, ev[c], 0);
        pool_kernel<<<POOL_BLKS_PER_CHUNK, 256, 0, s2>>>(
            idx, ux, (float*)d_out, c * POOL_BLKS_PER_CHUNK);
    }
    cudaEventRecord(evJoin, s2);
    cudaStreamWaitEvent(0, evJoin, 0);
}

// round 6
// speedup vs baseline: 2.1663x; 2.1663x over previous
#include <cuda_runtime.h>
#include <cstdint>

// Problem constants (fixed by the dataset)
#define BB   16
#define NN   4096
#define SS   1024
#define KK   32
#define DIN  64
#define DINC 67
#define DOUT 64

// Scratch (static device globals: allocation-free per harness rules)
__device__ float g_sum[(size_t)BB * NN * DOUT];   // xc@W1 + bias (+ xp if use_x)
__device__ float g_xp [(size_t)BB * NN * DOUT];   // xp = x@W2 (center subtraction)

// ---------------------------------------------------------------------------
// SMEM layout for proj_mma (float offsets)
//   B-operand bufs (weights):  [kstep][n:64][4 x float4]   (hi/lo interleaved)
//   A-operand bufs (acts):     [kstep][r:128][4 x float4]
// float4 atom at (row, g): { hi(k=g), hi(k=g+4), lo(k=g), lo(k=g+4) }
// with XOR swizzle g_store = g ^ (row & 3)  -> conflict-free LDS.128
// ---------------------------------------------------------------------------
#define SW2F 0                      //  8 ksteps * 64 * 16 = 8192
#define SW1F 8192                   //  9 ksteps * 64 * 16 = 9216
#define SBF  17408                  //  64
#define SAXF 17472                  //  8 ksteps * 128 * 16 = 16384
#define SACF 33856                  //  9 ksteps * 128 * 16 = 18432
#define SMEM_FLOATS 52288
#define SMEM_BYTES  (SMEM_FLOATS * 4)   // 209152

__device__ __forceinline__ float4 ldA(const float* buf, int ks, int r, int g) {
    return ((const float4*)buf)[(ks * 128 + r) * 4 + (g ^ (r & 3))];
}
__device__ __forceinline__ float4 ldB(const float* buf, int ks, int n, int g) {
    return ((const float4*)buf)[(ks * 64 + n) * 4 + (g ^ (n & 3))];
}
__device__ __forceinline__ void stA(float* buf, int ks, int r, int kin, float hi, float lo) {
    int g = kin & 3, half = kin >> 2;
    float* p = buf + (((ks * 128 + r) * 4 + (g ^ (r & 3))) << 2);
    p[half] = hi; p[2 + half] = lo;
}
__device__ __forceinline__ void stB(float* buf, int ks, int n, int kin, float hi, float lo) {
    int g = kin & 3, half = kin >> 2;
    float* p = buf + (((ks * 64 + n) * 4 + (g ^ (n & 3))) << 2);
    p[half] = hi; p[2 + half] = lo;
}
__device__ __forceinline__ void split_f32(float v, float& hi, float& lo) {
    hi = __uint_as_float(__float_as_uint(v) & 0xFFFFE000u);   // exact tf32
    lo = v - hi;
}

// m16n8k8 tf32 MMA, D += A*B (D aliases C)
__device__ __forceinline__ void mma8(float* d, uint32_t a0, uint32_t a1, uint32_t a2,
                                     uint32_t a3, uint32_t b0, uint32_t b1) {
    asm volatile(
        "mma.sync.aligned.m16n8k8.row.col.f32.tf32.tf32.f32 "
        "{%0,%1,%2,%3}, {%4,%5,%6,%7}, {%8,%9}, {%0,%1,%2,%3};"
        : "+f"(d[0]), "+f"(d[1]), "+f"(d[2]), "+f"(d[3])
        : "r"(a0), "r"(a1), "r"(a2), "r"(a3), "r"(b0), "r"(b1));
}

// One GEMM phase: acc(2 m-tiles x 4 n-tiles) += A[128 x 8*nks] @ B[64 x 8*nks]^T
// with 3-term hi/lo split per k-step.
__device__ __forceinline__ void gemm_phase(
    const float* abuf, const float* bbuf, int nks,
    float acc[2][4][4], const int rA[2], const int nI[4], int km)
{
    for (int ks = 0; ks < nks; ks++) {
        float4 A0[2], A1[2], Bv[4];
        #pragma unroll
        for (int tM = 0; tM < 2; tM++) {
            A0[tM] = ldA(abuf, ks, rA[tM],     km);   // a0h,a2h,a0l,a2l
            A1[tM] = ldA(abuf, ks, rA[tM] + 8, km);   // a1h,a3h,a1l,a3l
        }
        #pragma unroll
        for (int tN = 0; tN < 4; tN++) Bv[tN] = ldB(bbuf, ks, nI[tN], km);   // b0h,b1h,b0l,b1l

        #pragma unroll
        for (int tM = 0; tM < 2; tM++) {
            uint32_t ah0 = __float_as_uint(A0[tM].x), ah1 = __float_as_uint(A1[tM].x);
            uint32_t ah2 = __float_as_uint(A0[tM].y), ah3 = __float_as_uint(A1[tM].y);
            uint32_t al0 = __float_as_uint(A0[tM].z), al1 = __float_as_uint(A1[tM].z);
            uint32_t al2 = __float_as_uint(A0[tM].w), al3 = __float_as_uint(A1[tM].w);
            #pragma unroll
            for (int tN = 0; tN < 4; tN++) {
                uint32_t bh0 = __float_as_uint(Bv[tN].x), bh1 = __float_as_uint(Bv[tN].y);
                uint32_t bl0 = __float_as_uint(Bv[tN].z), bl1 = __float_as_uint(Bv[tN].w);
                mma8(acc[tM][tN], ah0, ah1, ah2, ah3, bh0, bh1);
                mma8(acc[tM][tN], ah0, ah1, ah2, ah3, bl0, bl1);
                mma8(acc[tM][tN], al0, al1, al2, al3, bh0, bh1);
            }
        }
    }
}

// ---------------------------------------------------------------------------
// proj_mma: per CTA computes 128 rows of g_xp and g_sum via HMMA tf32 split.
// ---------------------------------------------------------------------------
__global__ void __launch_bounds__(256) proj_mma(
    const float* __restrict__ x, const float* __restrict__ xcm,
    const float* __restrict__ w1, const float* __restrict__ w2,
    const float* __restrict__ bias, const int* __restrict__ use_x)
{
    extern __shared__ float sm[];
    float* sW2 = sm + SW2F;
    float* sW1 = sm + SW1F;
    float* sB  = sm + SBF;
    float* sAX = sm + SAXF;
    float* sAC = sm + SACF;

    const int tid  = threadIdx.x;
    const int wid  = tid >> 5;
    const int lane = tid & 31;
    const int ux   = use_x[0];
    const size_t base = (size_t)blockIdx.x * 128;

    // ---- stage W2 [64][64] ----
    for (int i = tid; i < 64 * 64; i += 256) {
        int n = i >> 6, k = i & 63;
        float hi, lo; split_f32(w2[i], hi, lo);
        stB(sW2, k >> 3, n, k & 7, hi, lo);
    }
    // ---- stage W1 [64][67], K padded to 72 ----
    for (int i = tid; i < 64 * 72; i += 256) {
        int n = i / 72, k = i - n * 72;
        float v = (k < DINC) ? w1[n * DINC + k] : 0.0f;
        float hi, lo; split_f32(v, hi, lo);
        stB(sW1, k >> 3, n, k & 7, hi, lo);
    }
    if (tid < DOUT) sB[tid] = bias[tid];
    // ---- stage x tile [128][64] ----
    if (ux) {
        const float* src = x + base * DIN;
        for (int i = tid; i < 128 * 64; i += 256) {
            int r = i >> 6, k = i & 63;
            float hi, lo; split_f32(src[i], hi, lo);
            stA(sAX, k >> 3, r, k & 7, hi, lo);
        }
    }
    // ---- stage xc tile [128][67], K padded to 72 ----
    {
        const float* src = xcm + base * DINC;
        for (int i = tid; i < 128 * 72; i += 256) {
            int r = i / 72, k = i - r * 72;
            float v = (k < DINC) ? src[r * DINC + k] : 0.0f;
            float hi, lo; split_f32(v, hi, lo);
            stA(sAC, k >> 3, r, k & 7, hi, lo);
        }
    }
    __syncthreads();

    // ---- per-warp fragment coordinates ----
    const int warpM = wid >> 1;            // 0..3
    const int warpN = wid & 1;             // 0..1
    const int km    = lane & 3;
    const int qr    = lane >> 2;           // 0..7
    int rA[2], nI[4];
    #pragma unroll
    for (int tM = 0; tM < 2; tM++) rA[tM] = warpM * 32 + tM * 16 + qr;
    #pragma unroll
    for (int tN = 0; tN < 4; tN++) nI[tN] = warpN * 32 + tN * 8 + qr;

    float acc[2][4][4];
    #pragma unroll
    for (int i = 0; i < 2; i++)
        #pragma unroll
        for (int j = 0; j < 4; j++)
            #pragma unroll
            for (int q = 0; q < 4; q++) acc[i][j][q] = 0.0f;

    const int colq = 2 * (lane & 3);       // c-frag column pair base

    // ---- Phase A: acc = x @ W2^T ; write g_xp ----
    if (ux) {
        gemm_phase(sAX, sW2, 8, acc, rA, nI, km);
        #pragma unroll
        for (int tM = 0; tM < 2; tM++) {
            int r = warpM * 32 + tM * 16 + qr;
            #pragma unroll
            for (int tN = 0; tN < 4; tN++) {
                int cc = warpN * 32 + tN * 8 + colq;
                float* p = g_xp + (base + r) * DOUT + cc;
                *(float2*)p = make_float2(acc[tM][tN][0], acc[tM][tN][1]);
                *(float2*)(p + 8 * DOUT) = make_float2(acc[tM][tN][2], acc[tM][tN][3]);
            }
        }
    }

    // ---- Phase B: acc += xc @ W1^T ; write g_sum = acc + bias ----
    gemm_phase(sAC, sW1, 9, acc, rA, nI, km);

    #pragma unroll
    for (int tM = 0; tM < 2; tM++) {
        int r = warpM * 32 + tM * 16 + qr;
        #pragma unroll
        for (int tN = 0; tN < 4; tN++) {
            int cc = warpN * 32 + tN * 8 + colq;
            float2 bv = *(const float2*)(sB + cc);
            float* p = g_sum + (base + r) * DOUT + cc;
            *(float2*)p = make_float2(acc[tM][tN][0] + bv.x, acc[tM][tN][1] + bv.y);
            *(float2*)(p + 8 * DOUT) = make_float2(acc[tM][tN][2] + bv.x, acc[tM][tN][3] + bv.y);
        }
    }
}

// ---------------------------------------------------------------------------
// Pool kernel (round-3 version: near its L2-traffic floor).
// ---------------------------------------------------------------------------
__global__ void __launch_bounds__(256) pool_kernel(
    const void* __restrict__ indexes, const int* __restrict__ use_x,
    float* __restrict__ out)
{
    __shared__ int sidx[512];           // 16 pairs x 32 idx
    const int tid = threadIdx.x;
    const size_t blk = blockIdx.x;      // 1024 blocks

    // dtype detection: reads in-bounds under BOTH interpretations
    int2 v = ((const int2*)indexes)[blk * 256 + tid];
    bool pok = (v.y == (v.x < 0 ? -1 : 0));
    int is64 = __syncthreads_and(pok);

    if (is64) {
        longlong2 q = ((const longlong2*)indexes)[blk * 256 + tid];
        sidx[2 * tid]     = (int)q.x;
        sidx[2 * tid + 1] = (int)q.y;
    } else {
        sidx[2 * tid]     = v.x;
        sidx[2 * tid + 1] = v.y;
    }
    __syncthreads();

    const int grp    = tid >> 4;
    const int lane16 = tid & 15;
    const size_t p   = blk * 16 + grp;
    const int b      = (int)(p >> 10);
    const int* myidx = sidx + grp * 32;

    const float* sumb = g_sum + (size_t)b * NN * DOUT;
    const int c0 = lane16 * 4;
    const int id0 = myidx[0];

    const int ux = use_x[0];
    float4 cen = make_float4(0.f, 0.f, 0.f, 0.f);
    if (ux)
        cen = *(const float4*)(g_xp + ((size_t)b * NN + id0) * DOUT + c0);

    float4 a[8];
    #pragma unroll
    for (int q = 0; q < 8; q++) a[q] = make_float4(-3.4e38f, -3.4e38f, -3.4e38f, -3.4e38f);

    #pragma unroll
    for (int q = 0; q < 8; q++) {
        int4 iq = ((const int4*)myidx)[q];
        int j0 = iq.x < 0 ? id0 : iq.x;
        int j1 = iq.y < 0 ? id0 : iq.y;
        int j2 = iq.z < 0 ? id0 : iq.z;
        int j3 = iq.w < 0 ? id0 : iq.w;
        float4 v0 = *(const float4*)(sumb + (size_t)j0 * DOUT + c0);
        float4 v1 = *(const float4*)(sumb + (size_t)j1 * DOUT + c0);
        float4 v2 = *(const float4*)(sumb + (size_t)j2 * DOUT + c0);
        float4 v3 = *(const float4*)(sumb + (size_t)j3 * DOUT + c0);
        float4 m01, m23;
        m01.x = fmaxf(v0.x, v1.x); m01.y = fmaxf(v0.y, v1.y); m01.z = fmaxf(v0.z, v1.z); m01.w = fmaxf(v0.w, v1.w);
        m23.x = fmaxf(v2.x, v3.x); m23.y = fmaxf(v2.y, v3.y); m23.z = fmaxf(v2.z, v3.z); m23.w = fmaxf(v2.w, v3.w);
        a[q].x = fmaxf(m01.x, m23.x); a[q].y = fmaxf(m01.y, m23.y);
        a[q].z = fmaxf(m01.z, m23.z); a[q].w = fmaxf(m01.w, m23.w);
    }

    #pragma unroll
    for (int st = 4; st > 0; st >>= 1)
        #pragma unroll
        for (int q = 0; q < st; q++) {
            a[q].x = fmaxf(a[q].x, a[q + st].x);
            a[q].y = fmaxf(a[q].y, a[q + st].y);
            a[q].z = fmaxf(a[q].z, a[q + st].z);
            a[q].w = fmaxf(a[q].w, a[q + st].w);
        }

    float4 o = make_float4(a[0].x - cen.x, a[0].y - cen.y, a[0].z - cen.z, a[0].w - cen.w);
    *(float4*)(out + p * DOUT + c0) = o;
}

// ---------------------------------------------------------------------------
// Launcher (single stream — multi-stream chunking regressed badly in R5)
// ---------------------------------------------------------------------------
extern "C" void kernel_launch(void* const* d_in, const int* in_sizes, int n_in,
                              void* d_out, int out_size)
{
    const float* x    = (const float*)d_in[0];
    const float* xcm  = (const float*)d_in[1];
    const void*  idx  = d_in[2];
    const float* w1   = (const float*)d_in[3];
    const float* w2   = (const float*)d_in[4];
    const float* bias = (const float*)d_in[5];
    const int*   ux   = (const int*)d_in[6];

    cudaFuncSetAttribute(proj_mma, cudaFuncAttributeMaxDynamicSharedMemorySize, SMEM_BYTES);

    proj_mma<<<(BB * NN) / 128, 256, SMEM_BYTES>>>(x, xcm, w1, w2, bias, ux);
    pool_kernel<<<(BB * SS) / 16, 256>>>(idx, ux, (float*)d_out);
}

// round 7
// speedup vs baseline: 3.5390x; 1.6337x over previous
#include <cuda_runtime.h>
#include <cstdint>

// Problem constants (fixed by the dataset)
#define BB   16
#define NN   4096
#define SS   1024
#define KK   32
#define DIN  64
#define DINC 67
#define DOUT 64

#define KS_A 4            // k16 steps for K=64 (x @ W2)
#define KS_B 5            // k16 steps for K=67 padded to 80 (xc @ W1)

// Scratch (static device globals: allocation-free per harness rules)
__device__ float g_sum[(size_t)BB * NN * DOUT];   // xc@W1 + bias (+ xp if use_x)
__device__ float g_xp [(size_t)BB * NN * DOUT];   // xp = x@W2 (center subtraction)

// ---------------------------------------------------------------------------
// SMEM layout (bytes). Atom at (row, g) = uint4 {hp(pair g), hp(pair g+4),
// lp(pair g), lp(pair g+4)} where pair j = bf16x2 of k=2j,2j+1.
// Swizzle: stored g' = g ^ (row & 3)  -> conflict-free LDS.128 for fragments.
//   A bufs: [kstep][row:128][4 x uint4];  B bufs: [kstep][n:64][4 x uint4]
// ---------------------------------------------------------------------------
#define SW2B 0                          // KS_A*64*64  = 16384
#define SW1B 16384                      // KS_B*64*64  = 20480
#define SAXB 36864                      // KS_A*128*64 = 32768
#define SACB 69632                      // KS_B*128*64 = 40960
#define SBIASB 110592                   // 256
#define SMEM_BYTES 110848

// pack two f32 into bf16x2 (round-to-nearest): lo half = v0, hi half = v1
__device__ __forceinline__ uint32_t pack_bf16x2(float v1_hi, float v0_lo) {
    uint32_t r;
    asm("cvt.rn.bf16x2.f32 %0, %1, %2;" : "=r"(r) : "f"(v1_hi), "f"(v0_lo));
    return r;
}
__device__ __forceinline__ void split_pair(float v0, float v1, uint32_t& hp, uint32_t& lp) {
    hp = pack_bf16x2(v1, v0);
    float h0 = __uint_as_float(hp << 16);
    float h1 = __uint_as_float(hp & 0xFFFF0000u);
    lp = pack_bf16x2(v1 - h1, v0 - h0);
}
// store one split pair into an operand buffer (R = rows in tile: 128 or 64)
__device__ __forceinline__ void st_pair(uint32_t* buf, int R, int ks, int row, int j,
                                        uint32_t hp, uint32_t lp) {
    int a = ((ks * R + row) * 4 + ((j & 3) ^ (row & 3))) * 4 + (j >> 2);
    buf[a] = hp; buf[a + 2] = lp;
}

// m16n8k16 bf16 MMA, D += A*B (D aliases C)
__device__ __forceinline__ void mma16(float* d, uint32_t a0, uint32_t a1, uint32_t a2,
                                      uint32_t a3, uint32_t b0, uint32_t b1) {
    asm volatile(
        "mma.sync.aligned.m16n8k16.row.col.f32.bf16.bf16.f32 "
        "{%0,%1,%2,%3}, {%4,%5,%6,%7}, {%8,%9}, {%0,%1,%2,%3};"
        : "+f"(d[0]), "+f"(d[1]), "+f"(d[2]), "+f"(d[3])
        : "r"(a0), "r"(a1), "r"(a2), "r"(a3), "r"(b0), "r"(b1));
}

// One GEMM phase with 3-term hi/lo split; MMA order = term-major, tile-minor
// so same-accumulator MMAs are 8 apart (dep distance 8).
__device__ __forceinline__ void gemm_phase(
    const uint4* abuf, const uint4* bbuf, int nks,
    float acc[2][4][4], const int rA[2], const int nI[4], int km)
{
    for (int ks = 0; ks < nks; ks++) {
        uint4 A0[2], A1[2], Bv[4];
        #pragma unroll
        for (int tM = 0; tM < 2; tM++) {
            int r0 = rA[tM], r1 = rA[tM] + 8;
            A0[tM] = abuf[(ks * 128 + r0) * 4 + (km ^ (r0 & 3))];
            A1[tM] = abuf[(ks * 128 + r1) * 4 + (km ^ (r1 & 3))];
        }
        #pragma unroll
        for (int tN = 0; tN < 4; tN++) {
            int n = nI[tN];
            Bv[tN] = bbuf[(ks * 64 + n) * 4 + (km ^ (n & 3))];
        }
        // term 1: Ah * Bh
        #pragma unroll
        for (int tM = 0; tM < 2; tM++)
            #pragma unroll
            for (int tN = 0; tN < 4; tN++)
                mma16(acc[tM][tN], A0[tM].x, A1[tM].x, A0[tM].y, A1[tM].y, Bv[tN].x, Bv[tN].y);
        // term 2: Ah * Bl
        #pragma unroll
        for (int tM = 0; tM < 2; tM++)
            #pragma unroll
            for (int tN = 0; tN < 4; tN++)
                mma16(acc[tM][tN], A0[tM].x, A1[tM].x, A0[tM].y, A1[tM].y, Bv[tN].z, Bv[tN].w);
        // term 3: Al * Bh
        #pragma unroll
        for (int tM = 0; tM < 2; tM++)
            #pragma unroll
            for (int tN = 0; tN < 4; tN++)
                mma16(acc[tM][tN], A0[tM].z, A1[tM].z, A0[tM].w, A1[tM].w, Bv[tN].x, Bv[tN].y);
    }
}

// ---------------------------------------------------------------------------
// proj_mma: per CTA computes 128 rows of g_xp and g_sum via bf16 split MMA.
// ---------------------------------------------------------------------------
__global__ void __launch_bounds__(256) proj_mma(
    const float* __restrict__ x, const float* __restrict__ xcm,
    const float* __restrict__ w1, const float* __restrict__ w2,
    const float* __restrict__ bias, const int* __restrict__ use_x)
{
    extern __shared__ char smem[];
    uint32_t* sW2 = (uint32_t*)(smem + SW2B);
    uint32_t* sW1 = (uint32_t*)(smem + SW1B);
    uint32_t* sAX = (uint32_t*)(smem + SAXB);
    uint32_t* sAC = (uint32_t*)(smem + SACB);
    float*    sB  = (float*)(smem + SBIASB);

    const int tid  = threadIdx.x;
    const int wid  = tid >> 5;
    const int lane = tid & 31;
    const int ux   = use_x[0];
    const size_t base = (size_t)blockIdx.x * 128;

    // ---- stage W2 [64 n][64 k] ----
    for (int i = tid; i < 64 * 32; i += 256) {
        int n = i >> 5, j = i & 31;
        const float* p = w2 + n * DIN + 2 * j;
        uint32_t hp, lp; split_pair(p[0], p[1], hp, lp);
        st_pair(sW2, 64, j >> 3, n, j & 7, hp, lp);
    }
    // ---- stage W1 [64 n][67 k -> 80] ----
    for (int i = tid; i < 64 * 40; i += 256) {
        int n = i / 40, j = i - n * 40;
        int k0 = 2 * j;
        float v0 = (k0     < DINC) ? w1[n * DINC + k0]     : 0.0f;
        float v1 = (k0 + 1 < DINC) ? w1[n * DINC + k0 + 1] : 0.0f;
        uint32_t hp, lp; split_pair(v0, v1, hp, lp);
        st_pair(sW1, 64, j >> 3, n, j & 7, hp, lp);
    }
    if (tid < DOUT) sB[tid] = bias[tid];
    // ---- stage x tile [128][64] ----
    if (ux) {
        const float* src = x + base * DIN;
        for (int i = tid; i < 128 * 32; i += 256) {
            int r = i >> 5, j = i & 31;
            const float* p = src + r * DIN + 2 * j;
            uint32_t hp, lp; split_pair(p[0], p[1], hp, lp);
            st_pair(sAX, 128, j >> 3, r, j & 7, hp, lp);
        }
    }
    // ---- stage xc tile [128][67 -> 80] ----
    {
        const float* src = xcm + base * DINC;
        for (int i = tid; i < 128 * 40; i += 256) {
            int r = i / 40, j = i - r * 40;
            int k0 = 2 * j;
            float v0 = (k0     < DINC) ? src[r * DINC + k0]     : 0.0f;
            float v1 = (k0 + 1 < DINC) ? src[r * DINC + k0 + 1] : 0.0f;
            uint32_t hp, lp; split_pair(v0, v1, hp, lp);
            st_pair(sAC, 128, j >> 3, r, j & 7, hp, lp);
        }
    }
    __syncthreads();

    // ---- per-warp fragment coordinates (warp grid 4M x 2N; 32x32 per warp) --
    const int warpM = wid >> 1;            // 0..3
    const int warpN = wid & 1;             // 0..1
    const int km    = lane & 3;            // k-pair selector
    const int qr    = lane >> 2;           // 0..7
    int rA[2], nI[4];
    #pragma unroll
    for (int tM = 0; tM < 2; tM++) rA[tM] = warpM * 32 + tM * 16 + qr;
    #pragma unroll
    for (int tN = 0; tN < 4; tN++) nI[tN] = warpN * 32 + tN * 8 + qr;

    float acc[2][4][4];
    #pragma unroll
    for (int i = 0; i < 2; i++)
        #pragma unroll
        for (int j = 0; j < 4; j++)
            #pragma unroll
            for (int q = 0; q < 4; q++) acc[i][j][q] = 0.0f;

    const int colq = 2 * (lane & 3);

    // ---- Phase A: acc = x @ W2^T ; write g_xp ----
    if (ux) {
        gemm_phase((const uint4*)sAX, (const uint4*)sW2, KS_A, acc, rA, nI, km);
        #pragma unroll
        for (int tM = 0; tM < 2; tM++) {
            int r = rA[tM];
            #pragma unroll
            for (int tN = 0; tN < 4; tN++) {
                int cc = warpN * 32 + tN * 8 + colq;
                float* p = g_xp + (base + r) * DOUT + cc;
                *(float2*)p = make_float2(acc[tM][tN][0], acc[tM][tN][1]);
                *(float2*)(p + 8 * DOUT) = make_float2(acc[tM][tN][2], acc[tM][tN][3]);
            }
        }
    }

    // ---- Phase B: acc += xc @ W1^T ; write g_sum = acc + bias ----
    gemm_phase((const uint4*)sAC, (const uint4*)sW1, KS_B, acc, rA, nI, km);

    #pragma unroll
    for (int tM = 0; tM < 2; tM++) {
        int r = rA[tM];
        #pragma unroll
        for (int tN = 0; tN < 4; tN++) {
            int cc = warpN * 32 + tN * 8 + colq;
            float2 bv = *(const float2*)(sB + cc);
            float* p = g_sum + (base + r) * DOUT + cc;
            *(float2*)p = make_float2(acc[tM][tN][0] + bv.x, acc[tM][tN][1] + bv.y);
            *(float2*)(p + 8 * DOUT) = make_float2(acc[tM][tN][2] + bv.x, acc[tM][tN][3] + bv.y);
        }
    }
}

// ---------------------------------------------------------------------------
// Pool kernel (round-3 version: proven 14.2us, near L2-traffic floor).
// ---------------------------------------------------------------------------
__global__ void __launch_bounds__(256) pool_kernel(
    const void* __restrict__ indexes, const int* __restrict__ use_x,
    float* __restrict__ out)
{
    __shared__ int sidx[512];           // 16 pairs x 32 idx
    const int tid = threadIdx.x;
    const size_t blk = blockIdx.x;      // 1024 blocks

    // dtype detection: reads in-bounds under BOTH interpretations
    int2 v = ((const int2*)indexes)[blk * 256 + tid];
    bool pok = (v.y == (v.x < 0 ? -1 : 0));
    int is64 = __syncthreads_and(pok);

    if (is64) {
        longlong2 q = ((const longlong2*)indexes)[blk * 256 + tid];
        sidx[2 * tid]     = (int)q.x;
        sidx[2 * tid + 1] = (int)q.y;
    } else {
        sidx[2 * tid]     = v.x;
        sidx[2 * tid + 1] = v.y;
    }
    __syncthreads();

    const int grp    = tid >> 4;
    const int lane16 = tid & 15;
    const size_t p   = blk * 16 + grp;
    const int b      = (int)(p >> 10);
    const int* myidx = sidx + grp * 32;

    const float* sumb = g_sum + (size_t)b * NN * DOUT;
    const int c0 = lane16 * 4;
    const int id0 = myidx[0];

    const int ux = use_x[0];
    float4 cen = make_float4(0.f, 0.f, 0.f, 0.f);
    if (ux)
        cen = *(const float4*)(g_xp + ((size_t)b * NN + id0) * DOUT + c0);

    float4 a[8];
    #pragma unroll
    for (int q = 0; q < 8; q++) a[q] = make_float4(-3.4e38f, -3.4e38f, -3.4e38f, -3.4e38f);

    #pragma unroll
    for (int q = 0; q < 8; q++) {
        int4 iq = ((const int4*)myidx)[q];
        int j0 = iq.x < 0 ? id0 : iq.x;
        int j1 = iq.y < 0 ? id0 : iq.y;
        int j2 = iq.z < 0 ? id0 : iq.z;
        int j3 = iq.w < 0 ? id0 : iq.w;
        float4 v0 = *(const float4*)(sumb + (size_t)j0 * DOUT + c0);
        float4 v1 = *(const float4*)(sumb + (size_t)j1 * DOUT + c0);
        float4 v2 = *(const float4*)(sumb + (size_t)j2 * DOUT + c0);
        float4 v3 = *(const float4*)(sumb + (size_t)j3 * DOUT + c0);
        float4 m01, m23;
        m01.x = fmaxf(v0.x, v1.x); m01.y = fmaxf(v0.y, v1.y); m01.z = fmaxf(v0.z, v1.z); m01.w = fmaxf(v0.w, v1.w);
        m23.x = fmaxf(v2.x, v3.x); m23.y = fmaxf(v2.y, v3.y); m23.z = fmaxf(v2.z, v3.z); m23.w = fmaxf(v2.w, v3.w);
        a[q].x = fmaxf(m01.x, m23.x); a[q].y = fmaxf(m01.y, m23.y);
        a[q].z = fmaxf(m01.z, m23.z); a[q].w = fmaxf(m01.w, m23.w);
    }

    #pragma unroll
    for (int st = 4; st > 0; st >>= 1)
        #pragma unroll
        for (int q = 0; q < st; q++) {
            a[q].x = fmaxf(a[q].x, a[q + st].x);
            a[q].y = fmaxf(a[q].y, a[q + st].y);
            a[q].z = fmaxf(a[q].z, a[q + st].z);
            a[q].w = fmaxf(a[q].w, a[q + st].w);
        }

    float4 o = make_float4(a[0].x - cen.x, a[0].y - cen.y, a[0].z - cen.z, a[0].w - cen.w);
    *(float4*)(out + p * DOUT + c0) = o;
}

// ---------------------------------------------------------------------------
// Launcher (single stream)
// ---------------------------------------------------------------------------
extern "C" void kernel_launch(void* const* d_in, const int* in_sizes, int n_in,
                              void* d_out, int out_size)
{
    const float* x    = (const float*)d_in[0];
    const float* xcm  = (const float*)d_in[1];
    const void*  idx  = d_in[2];
    const float* w1   = (const float*)d_in[3];
    const float* w2   = (const float*)d_in[4];
    const float* bias = (const float*)d_in[5];
    const int*   ux   = (const int*)d_in[6];

    cudaFuncSetAttribute(proj_mma, cudaFuncAttributeMaxDynamicSharedMemorySize, SMEM_BYTES);

    proj_mma<<<(BB * NN) / 128, 256, SMEM_BYTES>>>(x, xcm, w1, w2, bias, ux);
    pool_kernel<<<(BB * SS) / 16, 256>>>(idx, ux, (float*)d_out);
}